// round 5
// baseline (speedup 1.0000x reference)
#include <cuda_runtime.h>
#include <cstdint>

// LSTM B=8192, T=128, I=32, H=64, OUT=8.
// Warp-specialized, batch-row-pipelined persistent CTA:
//   warps 0-7 : MMA (tf32 m16n8k8), full Wcat (96x256) register-resident
//   warps 8-11: activations (tanh.approx) + state update + x staging
// Two row groups of 32 alternate between the roles each phase.

#define B_TOT 8192
#define T_LEN 128
#define I_SZ  32
#define H_SZ  64
#define OUT_SZ 8
#define M_BLK 64
#define M_G   32
#define NTHREADS 384

#define PX 36     // x tile pitch (words): 4*arl+akl conflict-free frag loads
#define PH 68     // h / c tile pitch
#define PG 260    // gates tile pitch (256 cols + pad)

// dynamic smem layout (word offsets)
#define XS_OFF(g) ((g) * (M_G * PX))
#define HS_BASE   (2 * M_G * PX)
#define HS_OFF(g) (HS_BASE + (g) * (M_G * PH))
#define CS_BASE   (HS_BASE + 2 * M_G * PH)
#define CS_OFF(g) (CS_BASE + (g) * (M_G * PH))
#define GT_BASE   (CS_BASE + 2 * M_G * PH)
#define GT_OFF(g) (GT_BASE + (g) * (M_G * PG))
#define SMEM_WORDS (GT_BASE + 2 * M_G * PG)

__device__ __forceinline__ uint32_t f2tf32(float f) {
    uint32_t r;
    asm("cvt.rna.tf32.f32 %0, %1;" : "=r"(r) : "f"(f));
    return r;
}
__device__ __forceinline__ float tanhhw(float x) {
    float y;
    asm("tanh.approx.f32 %0, %1;" : "=f"(y) : "f"(x));
    return y;
}
__device__ __forceinline__ void mma_tf32(float c[4],
                                         uint32_t a0, uint32_t a1, uint32_t a2, uint32_t a3,
                                         uint32_t b0, uint32_t b1) {
    asm("mma.sync.aligned.m16n8k8.row.col.f32.tf32.tf32.f32 "
        "{%0,%1,%2,%3},{%4,%5,%6,%7},{%8,%9},{%0,%1,%2,%3};"
        : "+f"(c[0]), "+f"(c[1]), "+f"(c[2]), "+f"(c[3])
        : "r"(a0), "r"(a1), "r"(a2), "r"(a3), "r"(b0), "r"(b1));
}

// gates[32,256] = [x_t(g) | h(g)] @ Wcat + bias  -> Gt[g]
__device__ __forceinline__ void mma_phase(uint32_t* sm, int g, int arl, int akl, int colw,
                                          const uint32_t bfr[4][12][2],
                                          const float bias2[4][2]) {
    const uint32_t* Xb = sm + XS_OFF(g);
    const uint32_t* Hb = sm + HS_OFF(g);
    float* Gt = reinterpret_cast<float*>(sm + GT_OFF(g));

    float acc[2][4][4];
    #pragma unroll
    for (int r = 0; r < 2; ++r)
        #pragma unroll
        for (int gg = 0; gg < 4; ++gg) {
            acc[r][gg][0] = bias2[gg][0];
            acc[r][gg][1] = bias2[gg][1];
            acc[r][gg][2] = bias2[gg][0];
            acc[r][gg][3] = bias2[gg][1];
        }

    #pragma unroll
    for (int q = 0; q < 12; ++q) {
        const uint32_t* Ab = (q < 4) ? Xb : Hb;
        const int pit = (q < 4) ? PX : PH;
        const int kk  = ((q < 4) ? q * 8 : (q - 4) * 8) + akl;
        #pragma unroll
        for (int r = 0; r < 2; ++r) {
            const int ar = r * 16 + arl;
            uint32_t a0 = Ab[ar * pit + kk];
            uint32_t a1 = Ab[(ar + 8) * pit + kk];
            uint32_t a2 = Ab[ar * pit + kk + 4];
            uint32_t a3 = Ab[(ar + 8) * pit + kk + 4];
            #pragma unroll
            for (int gg = 0; gg < 4; ++gg)
                mma_tf32(acc[r][gg], a0, a1, a2, a3, bfr[gg][q][0], bfr[gg][q][1]);
        }
    }

    #pragma unroll
    for (int r = 0; r < 2; ++r) {
        const int rr = r * 16 + arl;
        #pragma unroll
        for (int gg = 0; gg < 4; ++gg) {
            const int cb = gg * 64 + colw + 2 * akl;
            *reinterpret_cast<float2*>(&Gt[rr * PG + cb]) =
                make_float2(acc[r][gg][0], acc[r][gg][1]);
            *reinterpret_cast<float2*>(&Gt[(rr + 8) * PG + cb]) =
                make_float2(acc[r][gg][2], acc[r][gg][3]);
        }
    }
}

// act: gates(g) -> c,h update for 32x64 elements (128 act threads, 16 elems each)
__device__ __forceinline__ void act_phase(uint32_t* sm, int g, int arow, int ac0) {
    const float* Gb = reinterpret_cast<const float*>(sm + GT_OFF(g));
    float*       Cb = reinterpret_cast<float*>(sm + CS_OFF(g));
    uint32_t*    Hb = sm + HS_OFF(g);

    #pragma unroll
    for (int jb = 0; jb < 4; ++jb) {
        const int cc = ac0 + jb * 4;
        float4 vi = *reinterpret_cast<const float4*>(&Gb[arow * PG + cc]);
        float4 vf = *reinterpret_cast<const float4*>(&Gb[arow * PG + 64 + cc]);
        float4 vg = *reinterpret_cast<const float4*>(&Gb[arow * PG + 128 + cc]);
        float4 vo = *reinterpret_cast<const float4*>(&Gb[arow * PG + 192 + cc]);
        float4 c  = *reinterpret_cast<float4*>(&Cb[arow * PH + cc]);
        float h0, h1, h2, h3;
        {
            float i = fmaf(tanhhw(vi.x), 0.5f, 0.5f);
            float f = fmaf(tanhhw(vf.x), 0.5f, 0.5f);
            float gv = tanhhw(vg.x);
            float o = fmaf(tanhhw(vo.x), 0.5f, 0.5f);
            c.x = f * c.x + i * gv;  h0 = o * tanhhw(c.x);
        }
        {
            float i = fmaf(tanhhw(vi.y), 0.5f, 0.5f);
            float f = fmaf(tanhhw(vf.y), 0.5f, 0.5f);
            float gv = tanhhw(vg.y);
            float o = fmaf(tanhhw(vo.y), 0.5f, 0.5f);
            c.y = f * c.y + i * gv;  h1 = o * tanhhw(c.y);
        }
        {
            float i = fmaf(tanhhw(vi.z), 0.5f, 0.5f);
            float f = fmaf(tanhhw(vf.z), 0.5f, 0.5f);
            float gv = tanhhw(vg.z);
            float o = fmaf(tanhhw(vo.z), 0.5f, 0.5f);
            c.z = f * c.z + i * gv;  h2 = o * tanhhw(c.z);
        }
        {
            float i = fmaf(tanhhw(vi.w), 0.5f, 0.5f);
            float f = fmaf(tanhhw(vf.w), 0.5f, 0.5f);
            float gv = tanhhw(vg.w);
            float o = fmaf(tanhhw(vo.w), 0.5f, 0.5f);
            c.w = f * c.w + i * gv;  h3 = o * tanhhw(c.w);
        }
        *reinterpret_cast<float4*>(&Cb[arow * PH + cc]) = c;
        *reinterpret_cast<uint4*>(&Hb[arow * PH + cc]) =
            make_uint4(f2tf32(h0), f2tf32(h1), f2tf32(h2), f2tf32(h3));
    }
}

__device__ __forceinline__ void ldg_x8(float xr[8], const float* p) {
    float4 a = *reinterpret_cast<const float4*>(p);
    float4 b = *reinterpret_cast<const float4*>(p + 4);
    xr[0] = a.x; xr[1] = a.y; xr[2] = a.z; xr[3] = a.w;
    xr[4] = b.x; xr[5] = b.y; xr[6] = b.z; xr[7] = b.w;
}
__device__ __forceinline__ void sts_x8(uint32_t* d, const float xr[8]) {
    *reinterpret_cast<uint4*>(d) =
        make_uint4(f2tf32(xr[0]), f2tf32(xr[1]), f2tf32(xr[2]), f2tf32(xr[3]));
    *reinterpret_cast<uint4*>(d + 4) =
        make_uint4(f2tf32(xr[4]), f2tf32(xr[5]), f2tf32(xr[6]), f2tf32(xr[7]));
}

__global__ __launch_bounds__(NTHREADS, 1)
void lstm_ws_kernel(const float* __restrict__ x,
                    const float* __restrict__ W_ih,
                    const float* __restrict__ W_hh,
                    const float* __restrict__ b_ih,
                    const float* __restrict__ b_hh,
                    const float* __restrict__ W_fc,
                    const float* __restrict__ b_fc,
                    float* __restrict__ out) {
    extern __shared__ uint32_t sm[];
    const int tid  = threadIdx.x;
    const int warp = tid >> 5;
    const int lane = tid & 31;
    const int row0 = blockIdx.x * M_BLK;
    const bool is_mma = warp < 8;

    const int colw = warp * 8;
    const int arl  = lane >> 2;
    const int akl  = lane & 3;

    // ---- MMA warps: resident Wcat fragments; i/f/o gates pre-scaled by 0.5
    //      so sigmoid(x) = 0.5*tanh(acc)+0.5 with acc already = x/2 ----
    uint32_t bfr[4][12][2];
    float bias2[4][2];
    if (is_mma) {
        const int bc = colw + (lane >> 2);
        #pragma unroll
        for (int g = 0; g < 4; ++g) {
            const int gc = g * 64 + bc;
            const float s = (g == 2) ? 1.0f : 0.5f;
            #pragma unroll
            for (int q = 0; q < 12; ++q) {
                const int k0 = q * 8 + (lane & 3);
                const int k1 = k0 + 4;
                float w0 = (k0 < I_SZ) ? W_ih[gc * I_SZ + k0] : W_hh[gc * H_SZ + (k0 - I_SZ)];
                float w1 = (k1 < I_SZ) ? W_ih[gc * I_SZ + k1] : W_hh[gc * H_SZ + (k1 - I_SZ)];
                bfr[g][q][0] = f2tf32(w0 * s);
                bfr[g][q][1] = f2tf32(w1 * s);
            }
            const int c0 = g * 64 + colw + 2 * (lane & 3);
            bias2[g][0] = (b_ih[c0] + b_hh[c0]) * s;
            bias2[g][1] = (b_ih[c0 + 1] + b_hh[c0 + 1]) * s;
        }
    }

    // zero h and c for both groups
    for (int i = tid; i < 4 * M_G * PH; i += NTHREADS) sm[HS_BASE + i] = 0u;

    // ---- act warps: prologue x staging + prefetch ----
    const int a    = tid - 256;            // 0..127 for act warps
    const int arow = a >> 2;               // 0..31
    const int ab   = a & 3;
    const int axc  = ab * 8;               // staging col base
    const int ac0  = ab * 16;              // activation col base
    float xr0[8], xr1[8];
    if (!is_mma) {
        float tmp[8];
        ldg_x8(tmp, x + ((size_t)(row0 + arow) * T_LEN + 0) * I_SZ + axc);
        sts_x8(sm + XS_OFF(0) + arow * PX + axc, tmp);
        ldg_x8(tmp, x + ((size_t)(row0 + 32 + arow) * T_LEN + 0) * I_SZ + axc);
        sts_x8(sm + XS_OFF(1) + arow * PX + axc, tmp);
        ldg_x8(xr0, x + ((size_t)(row0 + arow) * T_LEN + 1) * I_SZ + axc);
        ldg_x8(xr1, x + ((size_t)(row0 + 32 + arow) * T_LEN + 1) * I_SZ + axc);
    }
    __syncthreads();

    // pipeline prologue: gates(G0, 0)
    if (is_mma) mma_phase(sm, 0, arl, akl, colw, bfr, bias2);
    __syncthreads();

    for (int t = 0; t < T_LEN; ++t) {
        // ---- Phase A: MMA gates(G1,t)  ||  act(G0,t) + stage x(G0,t+1) ----
        if (is_mma) {
            mma_phase(sm, 1, arl, akl, colw, bfr, bias2);
        } else {
            if (t < T_LEN - 1) sts_x8(sm + XS_OFF(0) + arow * PX + axc, xr0);
            if (t + 2 < T_LEN)
                ldg_x8(xr0, x + ((size_t)(row0 + arow) * T_LEN + (t + 2)) * I_SZ + axc);
            act_phase(sm, 0, arow, ac0);
        }
        __syncthreads();

        // ---- Phase B: MMA gates(G0,t+1) ||  act(G1,t) + stage x(G1,t+1) ----
        if (is_mma) {
            if (t < T_LEN - 1) mma_phase(sm, 0, arl, akl, colw, bfr, bias2);
        } else {
            if (t < T_LEN - 1) sts_x8(sm + XS_OFF(1) + arow * PX + axc, xr1);
            if (t + 2 < T_LEN)
                ldg_x8(xr1, x + ((size_t)(row0 + 32 + arow) * T_LEN + (t + 2)) * I_SZ + axc);
            act_phase(sm, 1, arow, ac0);
        }
        __syncthreads();
    }

    // ---- FC epilogue: out[row, o] = h_T . W_fc[o] + b_fc[o] ----
    for (int idx = tid; idx < M_BLK * OUT_SZ; idx += NTHREADS) {
        const int row = idx >> 3;
        const int o   = idx & 7;
        const int g   = row >> 5;
        const int lr  = row & 31;
        const uint32_t* hp = sm + HS_OFF(g) + lr * PH;
        const float* wf = W_fc + o * H_SZ;
        float s = b_fc[o];
        #pragma unroll
        for (int k = 0; k < H_SZ; ++k)
            s += __uint_as_float(hp[k]) * wf[k];
        out[(size_t)(row0 + row) * OUT_SZ + o] = s;
    }
}

extern "C" void kernel_launch(void* const* d_in, const int* in_sizes, int n_in,
                              void* d_out, int out_size) {
    const float* x    = (const float*)d_in[0];
    const float* W_ih = (const float*)d_in[1];
    const float* W_hh = (const float*)d_in[2];
    const float* b_ih = (const float*)d_in[3];
    const float* b_hh = (const float*)d_in[4];
    const float* W_fc = (const float*)d_in[5];
    const float* b_fc = (const float*)d_in[6];
    float* out = (float*)d_out;

    const size_t smem = SMEM_WORDS * sizeof(uint32_t);
    cudaFuncSetAttribute(lstm_ws_kernel, cudaFuncAttributeMaxDynamicSharedMemorySize, (int)smem);
    lstm_ws_kernel<<<B_TOT / M_BLK, NTHREADS, smem>>>(x, W_ih, W_hh, b_ih, b_hh, W_fc, b_fc, out);
}

// round 6
// speedup vs baseline: 1.4117x; 1.4117x over previous
#include <cuda_runtime.h>
#include <cstdint>

// LSTM B=8192, T=128, I=32, H=64, OUT=8.
// R6: two row groups of 32, per-thread interleaved pipeline:
//   phase A: mma(G1,t)   + act(G0,t) + stage x0
//   phase B: mma(G0,t+1) + act(G1,t) + stage x1
// Every warp carries both tensor (m16n8k8 tf32, Wcat register-resident) and
// MUFU (tanh.approx) work each phase; gates stay in registers.

#define B_TOT 8192
#define T_LEN 128
#define I_SZ  32
#define H_SZ  64
#define OUT_SZ 8
#define M_BLK 64
#define M_G   32
#define NTHREADS 256
#define PX 36     // pitch % 32 == 4 -> conflict-free frag LDS
#define PH 68

__device__ __forceinline__ uint32_t f2tf32(float f) {
    uint32_t r;
    asm("cvt.rna.tf32.f32 %0, %1;" : "=r"(r) : "f"(f));
    return r;
}
__device__ __forceinline__ float tanhhw(float x) {
    float y;
    asm("tanh.approx.f32 %0, %1;" : "=f"(y) : "f"(x));
    return y;
}
__device__ __forceinline__ void mma_tf32(float c[4],
                                         uint32_t a0, uint32_t a1, uint32_t a2, uint32_t a3,
                                         uint32_t b0, uint32_t b1) {
    asm("mma.sync.aligned.m16n8k8.row.col.f32.tf32.tf32.f32 "
        "{%0,%1,%2,%3},{%4,%5,%6,%7},{%8,%9},{%0,%1,%2,%3};"
        : "+f"(c[0]), "+f"(c[1]), "+f"(c[2]), "+f"(c[3])
        : "r"(a0), "r"(a1), "r"(a2), "r"(a3), "r"(b0), "r"(b1));
}

// one K=8 slice of the [32,96]x[96,256] gate GEMM
__device__ __forceinline__ void mma_q(float acc[2][4][4],
                                      const uint32_t* __restrict__ Ab, int pit, int kof,
                                      int arl, int akl,
                                      const uint32_t (&bfr)[4][12][2], int q) {
    const int kk = kof + akl;
    #pragma unroll
    for (int r = 0; r < 2; ++r) {
        const int ar = r * 16 + arl;
        uint32_t a0 = Ab[ar * pit + kk];
        uint32_t a1 = Ab[(ar + 8) * pit + kk];
        uint32_t a2 = Ab[ar * pit + kk + 4];
        uint32_t a3 = Ab[(ar + 8) * pit + kk + 4];
        #pragma unroll
        for (int g = 0; g < 4; ++g)
            mma_tf32(acc[r][g], a0, a1, a2, a3, bfr[g][q][0], bfr[g][q][1]);
    }
}

// activate 4 elems (one r-slice); acc for i/f/o gates pre-scaled by 0.5
__device__ __forceinline__ void act_r(const float acc[4][4], float cst[4], float hv[4]) {
    #pragma unroll
    for (int e = 0; e < 4; ++e) {
        float ig = fmaf(tanhhw(acc[0][e]), 0.5f, 0.5f);
        float fg = fmaf(tanhhw(acc[1][e]), 0.5f, 0.5f);
        float gg = tanhhw(acc[2][e]);
        float og = fmaf(tanhhw(acc[3][e]), 0.5f, 0.5f);
        float c  = fg * cst[e] + ig * gg;
        cst[e] = c;
        hv[e] = og * tanhhw(c);
    }
}

// One phase: fill accM from group GM tiles, consume accA (-> h of group GA),
// stage GA's x(t+1) from xr and prefetch xr <- x(t+2).
template <int GM, int GA>
__device__ __forceinline__ void phase_fn(
    uint32_t (&Xs)[2][M_G * PX], uint32_t (&Hs)[2][M_G * PH],
    float (&accM)[2][4][4], float (&accA)[2][4][4],
    float (&cst)[2][4], float4& xr, const float* __restrict__ xga, int t,
    int arl, int akl, int colw, int srow, int scol,
    const uint32_t (&bfr)[4][12][2], const float (&bias2)[4][2]) {
    const uint32_t* Xb = Xs[GM];
    const uint32_t* Hb = Hs[GM];

    // init accM with (pre-scaled) bias
    #pragma unroll
    for (int r = 0; r < 2; ++r)
        #pragma unroll
        for (int g = 0; g < 4; ++g) {
            accM[r][g][0] = bias2[g][0];
            accM[r][g][1] = bias2[g][1];
            accM[r][g][2] = bias2[g][0];
            accM[r][g][3] = bias2[g][1];
        }

    float hv0[4], hv1[4];

    // x-part of K (q=0..3) interleaved with act r=0
    mma_q(accM, Xb, PX, 0, arl, akl, bfr, 0);
    mma_q(accM, Xb, PX, 8, arl, akl, bfr, 1);
    act_r(accA[0], cst[0], hv0);
    mma_q(accM, Xb, PX, 16, arl, akl, bfr, 2);
    mma_q(accM, Xb, PX, 24, arl, akl, bfr, 3);

    // h-part q=4..7 interleaved with act r=1
    mma_q(accM, Hb, PH, 0, arl, akl, bfr, 4);
    mma_q(accM, Hb, PH, 8, arl, akl, bfr, 5);
    act_r(accA[1], cst[1], hv1);
    mma_q(accM, Hb, PH, 16, arl, akl, bfr, 6);
    mma_q(accM, Hb, PH, 24, arl, akl, bfr, 7);

    // stage x(GA, t+1) and prefetch x(GA, t+2)
    {
        uint32_t* xw = Xs[GA] + srow * PX + scol;
        *reinterpret_cast<uint4*>(xw) =
            make_uint4(f2tf32(xr.x), f2tf32(xr.y), f2tf32(xr.z), f2tf32(xr.w));
        int tt = t + 2 < T_LEN ? t + 2 : T_LEN - 1;
        xr = *reinterpret_cast<const float4*>(xga + (size_t)tt * I_SZ);
    }

    mma_q(accM, Hb, PH, 32, arl, akl, bfr, 8);
    mma_q(accM, Hb, PH, 40, arl, akl, bfr, 9);

    // h writeback (tf32) for group GA
    {
        uint32_t* hp = Hs[GA] + arl * PH + colw + 2 * akl;
        *reinterpret_cast<uint2*>(hp)          = make_uint2(f2tf32(hv0[0]), f2tf32(hv0[1]));
        *reinterpret_cast<uint2*>(hp + 8 * PH) = make_uint2(f2tf32(hv0[2]), f2tf32(hv0[3]));
        *reinterpret_cast<uint2*>(hp + 16 * PH) = make_uint2(f2tf32(hv1[0]), f2tf32(hv1[1]));
        *reinterpret_cast<uint2*>(hp + 24 * PH) = make_uint2(f2tf32(hv1[2]), f2tf32(hv1[3]));
    }

    mma_q(accM, Hb, PH, 48, arl, akl, bfr, 10);
    mma_q(accM, Hb, PH, 56, arl, akl, bfr, 11);
}

__global__ __launch_bounds__(NTHREADS, 1)
void lstm_ilv_kernel(const float* __restrict__ x,
                     const float* __restrict__ W_ih,
                     const float* __restrict__ W_hh,
                     const float* __restrict__ b_ih,
                     const float* __restrict__ b_hh,
                     const float* __restrict__ W_fc,
                     const float* __restrict__ b_fc,
                     float* __restrict__ out) {
    __shared__ __align__(16) uint32_t Xs[2][M_G * PX];
    __shared__ __align__(16) uint32_t Hs[2][M_G * PH];

    const int tid  = threadIdx.x;
    const int warp = tid >> 5;
    const int lane = tid & 31;
    const int row0 = blockIdx.x * M_BLK;
    const int colw = warp * 8;
    const int arl  = lane >> 2;
    const int akl  = lane & 3;

    // ---- resident Wcat fragments; i/f/o pre-scaled by 0.5 (tanh-sigmoid) ----
    uint32_t bfr[4][12][2];
    float bias2[4][2];
    {
        const int bc = colw + arl;
        #pragma unroll
        for (int g = 0; g < 4; ++g) {
            const int gc = g * 64 + bc;
            const float s = (g == 2) ? 1.0f : 0.5f;
            #pragma unroll
            for (int q = 0; q < 12; ++q) {
                const int k0 = q * 8 + akl;
                const int k1 = k0 + 4;
                float w0 = (k0 < I_SZ) ? W_ih[gc * I_SZ + k0] : W_hh[gc * H_SZ + (k0 - I_SZ)];
                float w1 = (k1 < I_SZ) ? W_ih[gc * I_SZ + k1] : W_hh[gc * H_SZ + (k1 - I_SZ)];
                bfr[g][q][0] = f2tf32(w0 * s);
                bfr[g][q][1] = f2tf32(w1 * s);
            }
            const int c0 = g * 64 + colw + 2 * akl;
            bias2[g][0] = (b_ih[c0] + b_hh[c0]) * s;
            bias2[g][1] = (b_ih[c0 + 1] + b_hh[c0 + 1]) * s;
        }
    }

    // zero h tiles (h0 = 0)
    for (int i = tid; i < 2 * M_G * PH; i += NTHREADS) Hs[0][i] = 0u;

    // ---- x staging ownership: one float4 per thread per group ----
    const int srow = tid >> 3;
    const int scol = (tid & 7) * 4;
    const float* xga0 = x + ((size_t)(row0 + srow) * T_LEN) * I_SZ + scol;
    const float* xga1 = x + ((size_t)(row0 + 32 + srow) * T_LEN) * I_SZ + scol;

    float4 xr0, xr1;
    {
        float4 v0 = *reinterpret_cast<const float4*>(xga0);
        float4 v1 = *reinterpret_cast<const float4*>(xga1);
        *reinterpret_cast<uint4*>(Xs[0] + srow * PX + scol) =
            make_uint4(f2tf32(v0.x), f2tf32(v0.y), f2tf32(v0.z), f2tf32(v0.w));
        *reinterpret_cast<uint4*>(Xs[1] + srow * PX + scol) =
            make_uint4(f2tf32(v1.x), f2tf32(v1.y), f2tf32(v1.z), f2tf32(v1.w));
        xr0 = *reinterpret_cast<const float4*>(xga0 + I_SZ);
        xr1 = *reinterpret_cast<const float4*>(xga1 + I_SZ);
    }

    float acc0[2][4][4], acc1[2][4][4];
    float cst0[2][4] = {}, cst1[2][4] = {};

    __syncthreads();

    // prologue: gates(G0, 0) -> acc0
    {
        #pragma unroll
        for (int r = 0; r < 2; ++r)
            #pragma unroll
            for (int g = 0; g < 4; ++g) {
                acc0[r][g][0] = bias2[g][0];
                acc0[r][g][1] = bias2[g][1];
                acc0[r][g][2] = bias2[g][0];
                acc0[r][g][3] = bias2[g][1];
            }
        #pragma unroll
        for (int q = 0; q < 4; ++q)
            mma_q(acc0, Xs[0], PX, q * 8, arl, akl, bfr, q);
        #pragma unroll
        for (int q = 4; q < 12; ++q)
            mma_q(acc0, Hs[0], PH, (q - 4) * 8, arl, akl, bfr, q);
    }
    __syncthreads();

    for (int t = 0; t < T_LEN; ++t) {
        // phase A: mma(G1,t) + act(G0,t)
        phase_fn<1, 0>(Xs, Hs, acc1, acc0, cst0, xr0, xga0, t,
                       arl, akl, colw, srow, scol, bfr, bias2);
        __syncthreads();
        // phase B: mma(G0,t+1) + act(G1,t)   (t=127 mma result unused)
        phase_fn<0, 1>(Xs, Hs, acc0, acc1, cst1, xr1, xga1, t,
                       arl, akl, colw, srow, scol, bfr, bias2);
        __syncthreads();
    }

    // ---- FC epilogue: out[row, o] = h_T . W_fc[o] + b_fc[o] ----
    for (int idx = tid; idx < M_BLK * OUT_SZ; idx += NTHREADS) {
        const int row = idx >> 3;
        const int o   = idx & 7;
        const int g   = row >> 5;
        const int lr  = row & 31;
        const uint32_t* hp = Hs[g] + lr * PH;
        const float* wf = W_fc + o * H_SZ;
        float s = b_fc[o];
        #pragma unroll
        for (int k = 0; k < H_SZ; ++k)
            s += __uint_as_float(hp[k]) * wf[k];
        out[(size_t)(row0 + row) * OUT_SZ + o] = s;
    }
}

extern "C" void kernel_launch(void* const* d_in, const int* in_sizes, int n_in,
                              void* d_out, int out_size) {
    const float* x    = (const float*)d_in[0];
    const float* W_ih = (const float*)d_in[1];
    const float* W_hh = (const float*)d_in[2];
    const float* b_ih = (const float*)d_in[3];
    const float* b_hh = (const float*)d_in[4];
    const float* W_fc = (const float*)d_in[5];
    const float* b_fc = (const float*)d_in[6];
    float* out = (float*)d_out;

    lstm_ilv_kernel<<<B_TOT / M_BLK, NTHREADS>>>(x, W_ih, W_hh, b_ih, b_hh, W_fc, b_fc, out);
}

// round 7
// speedup vs baseline: 2.6176x; 1.8543x over previous
#include <cuda_runtime.h>
#include <cuda_fp16.h>
#include <cstdint>

// LSTM B=8192, T=128, I=32, H=64, OUT=8.
// R7: fp16 m16n8k16 MMA (same 10-bit mantissa as tf32, 2x rate), frag-major
// smem layout so A-fragments load as single LDS.128. Two row groups of 32,
// per-thread interleaved mma/act pipeline (R6 structure), Wcat in registers.

#define B_TOT 8192
#define T_LEN 128
#define I_SZ  32
#define H_SZ  64
#define OUT_SZ 8
#define M_BLK 64
#define NTHREADS 256

// frag-major tiles: block(q,r) = 32 slots x 16B = 128 words; slot = lane.
// X tile/group: q 0..1, r 0..1 -> 512 words. H tile/group: q 0..3 -> 1024 words.

__device__ __forceinline__ uint32_t packh2(float a, float b) {
    __half2 h = __floats2half2_rn(a, b);   // .x = a (low, even col)
    return *reinterpret_cast<uint32_t*>(&h);
}
__device__ __forceinline__ float tanhhw(float x) {
    float y;
    asm("tanh.approx.f32 %0, %1;" : "=f"(y) : "f"(x));
    return y;
}
__device__ __forceinline__ void mma_f16(float c[4],
                                        uint32_t a0, uint32_t a1, uint32_t a2, uint32_t a3,
                                        uint32_t b0, uint32_t b1) {
    asm("mma.sync.aligned.m16n8k16.row.col.f32.f16.f16.f32 "
        "{%0,%1,%2,%3},{%4,%5,%6,%7},{%8,%9},{%0,%1,%2,%3};"
        : "+f"(c[0]), "+f"(c[1]), "+f"(c[2]), "+f"(c[3])
        : "r"(a0), "r"(a1), "r"(a2), "r"(a3), "r"(b0), "r"(b1));
}

// one (q, r) fragment: LDS.128 + 4 gate MMAs
__device__ __forceinline__ void frag_mma(float accr[4][4], const uint32_t* __restrict__ blk,
                                         int lane, const uint32_t (&bfr)[4][6][2], int q) {
    uint4 av = *reinterpret_cast<const uint4*>(blk + lane * 4);
    #pragma unroll
    for (int g = 0; g < 4; ++g)
        mma_f16(accr[g], av.x, av.y, av.z, av.w, bfr[g][q][0], bfr[g][q][1]);
}

// activate 4 elems; i/f/o accs pre-scaled by 0.5 (sigmoid = 0.5*tanh+0.5)
__device__ __forceinline__ void act_r(const float acc[4][4], float cst[4], float hv[4]) {
    #pragma unroll
    for (int e = 0; e < 4; ++e) {
        float ig = fmaf(tanhhw(acc[0][e]), 0.5f, 0.5f);
        float fg = fmaf(tanhhw(acc[1][e]), 0.5f, 0.5f);
        float gg = tanhhw(acc[2][e]);
        float og = fmaf(tanhhw(acc[3][e]), 0.5f, 0.5f);
        float c  = fg * cst[e] + ig * gg;
        cst[e] = c;
        hv[e] = og * tanhhw(c);
    }
}

// Phase: mma(group GM) into accM; act(accA -> h of group GA); stage x(GA,t+1).
template <int GM, int GA>
__device__ __forceinline__ void phase_fn(uint32_t* __restrict__ Xs, uint32_t* __restrict__ Hs,
                                         float (&accM)[2][4][4], float (&accA)[2][4][4],
                                         float (&cst)[2][4], float4& xr,
                                         const float* __restrict__ xga, int t, int lane,
                                         int xoff0, int xoff1, int hoff0, int hoff1,
                                         const uint32_t (&bfr)[4][6][2],
                                         const float (&bias2)[4][2]) {
    const uint32_t* Xm = Xs + GM * 512;
    const uint32_t* Hm = Hs + GM * 1024;

    #pragma unroll
    for (int r = 0; r < 2; ++r)
        #pragma unroll
        for (int g = 0; g < 4; ++g) {
            accM[r][g][0] = bias2[g][0];
            accM[r][g][1] = bias2[g][1];
            accM[r][g][2] = bias2[g][0];
            accM[r][g][3] = bias2[g][1];
        }

    float hv0[4], hv1[4];

    frag_mma(accM[0], Xm + 0,   lane, bfr, 0);
    frag_mma(accM[1], Xm + 128, lane, bfr, 0);
    frag_mma(accM[0], Xm + 256, lane, bfr, 1);
    frag_mma(accM[1], Xm + 384, lane, bfr, 1);
    act_r(accA[0], cst[0], hv0);
    frag_mma(accM[0], Hm + 0,   lane, bfr, 2);
    frag_mma(accM[1], Hm + 128, lane, bfr, 2);
    frag_mma(accM[0], Hm + 256, lane, bfr, 3);
    frag_mma(accM[1], Hm + 384, lane, bfr, 3);
    act_r(accA[1], cst[1], hv1);

    // stage x(GA, t+1) + prefetch x(GA, t+2)
    {
        uint32_t* Xa = Xs + GA * 512;
        Xa[xoff0] = packh2(xr.x, xr.y);
        Xa[xoff1] = packh2(xr.z, xr.w);
        int tt = (t + 2 < T_LEN) ? t + 2 : T_LEN - 1;
        xr = *reinterpret_cast<const float4*>(xga + (size_t)tt * I_SZ);
    }

    frag_mma(accM[0], Hm + 512, lane, bfr, 4);
    frag_mma(accM[1], Hm + 640, lane, bfr, 4);

    // h(GA) writeback: 2 x STS.64 into frag-major H tile
    {
        uint32_t* Ha = Hs + GA * 1024;
        *reinterpret_cast<uint2*>(Ha + hoff0) =
            make_uint2(packh2(hv0[0], hv0[1]), packh2(hv0[2], hv0[3]));
        *reinterpret_cast<uint2*>(Ha + hoff1) =
            make_uint2(packh2(hv1[0], hv1[1]), packh2(hv1[2], hv1[3]));
    }

    frag_mma(accM[0], Hm + 768, lane, bfr, 5);
    frag_mma(accM[1], Hm + 896, lane, bfr, 5);
}

__global__ __launch_bounds__(NTHREADS, 1)
void lstm_fp16_kernel(const float* __restrict__ x,
                      const float* __restrict__ W_ih,
                      const float* __restrict__ W_hh,
                      const float* __restrict__ b_ih,
                      const float* __restrict__ b_hh,
                      const float* __restrict__ W_fc,
                      const float* __restrict__ b_fc,
                      float* __restrict__ out) {
    __shared__ __align__(16) uint32_t Xs[2 * 512];
    __shared__ __align__(16) uint32_t Hs[2 * 1024];

    const int tid  = threadIdx.x;
    const int warp = tid >> 5;
    const int lane = tid & 31;
    const int row0 = blockIdx.x * M_BLK;
    const int colw = warp * 8;
    const int arl  = lane >> 2;   // frag row / B n-index
    const int akl  = lane & 3;    // frag k-group

    // ---- B fragments (fp16 half2), i/f/o pre-scaled by 0.5 ----
    // (g,q): n = g*64+colw+arl; k = q*16 + 2*akl + {0,1} (b0), +8 (b1)
    uint32_t bfr[4][6][2];
    float bias2[4][2];
    {
        const int gc_base = colw + arl;
        #pragma unroll
        for (int g = 0; g < 4; ++g) {
            const int gc = g * 64 + gc_base;
            const float s = (g == 2) ? 1.0f : 0.5f;
            #pragma unroll
            for (int q = 0; q < 6; ++q) {
                const int k0 = q * 16 + 2 * akl;
                float w[4];
                #pragma unroll
                for (int j = 0; j < 4; ++j) {
                    const int k = k0 + ((j < 2) ? j : j + 6);   // k0,k0+1,k0+8,k0+9
                    w[j] = (k < I_SZ) ? W_ih[gc * I_SZ + k] : W_hh[gc * H_SZ + (k - I_SZ)];
                }
                bfr[g][q][0] = packh2(w[0] * s, w[1] * s);
                bfr[g][q][1] = packh2(w[2] * s, w[3] * s);
            }
            const int c0 = g * 64 + colw + 2 * akl;
            bias2[g][0] = (b_ih[c0] + b_hh[c0]) * s;
            bias2[g][1] = (b_ih[c0 + 1] + b_hh[c0 + 1]) * s;
        }
    }

    // zero H tiles (h0 = 0)
    for (int i = tid; i < 2 * 1024; i += NTHREADS) Hs[i] = 0u;

    // ---- x staging ownership: float4 per thread per group ----
    const int srow = tid >> 3;           // 0..31
    const int scol = (tid & 7) * 4;      // 0..28
    int xoff0, xoff1;
    {
        const int qx = scol >> 4, rx = srow >> 4;
        const int arls = srow & 7, subx = (srow >> 3) & 1;
        const int p0 = (scol & 15) >> 1;          // {0,2,4,6}
        const int tg0 = p0 & 3, hfx = p0 >> 2;
        const int word = subx + 2 * hfx;
        xoff0 = (qx * 2 + rx) * 128 + (arls * 4 + tg0) * 4 + word;
        xoff1 = xoff0 + 4;
    }
    // h writeback offsets: qh = warp>>1, half = warp&1
    const int hoff0 = ((warp >> 1) * 2) * 128 + lane * 4 + 2 * (warp & 1);
    const int hoff1 = hoff0 + 128;

    const float* xga0 = x + ((size_t)(row0 + srow) * T_LEN) * I_SZ + scol;
    const float* xga1 = x + ((size_t)(row0 + 32 + srow) * T_LEN) * I_SZ + scol;

    float4 xr0, xr1;
    {
        float4 v0 = *reinterpret_cast<const float4*>(xga0);
        float4 v1 = *reinterpret_cast<const float4*>(xga1);
        Xs[xoff0]       = packh2(v0.x, v0.y);
        Xs[xoff1]       = packh2(v0.z, v0.w);
        Xs[512 + xoff0] = packh2(v1.x, v1.y);
        Xs[512 + xoff1] = packh2(v1.z, v1.w);
        xr0 = *reinterpret_cast<const float4*>(xga0 + I_SZ);
        xr1 = *reinterpret_cast<const float4*>(xga1 + I_SZ);
    }

    float acc0[2][4][4], acc1[2][4][4];
    float cst0[2][4] = {}, cst1[2][4] = {};

    __syncthreads();

    // prologue: gates(G0, 0) -> acc0
    {
        #pragma unroll
        for (int r = 0; r < 2; ++r)
            #pragma unroll
            for (int g = 0; g < 4; ++g) {
                acc0[r][g][0] = bias2[g][0];
                acc0[r][g][1] = bias2[g][1];
                acc0[r][g][2] = bias2[g][0];
                acc0[r][g][3] = bias2[g][1];
            }
        #pragma unroll
        for (int q = 0; q < 2; ++q)
            #pragma unroll
            for (int r = 0; r < 2; ++r)
                frag_mma(acc0[r], Xs + (q * 2 + r) * 128, lane, bfr, q);
        #pragma unroll
        for (int qh = 0; qh < 4; ++qh)
            #pragma unroll
            for (int r = 0; r < 2; ++r)
                frag_mma(acc0[r], Hs + (qh * 2 + r) * 128, lane, bfr, 2 + qh);
    }
    __syncthreads();

    for (int t = 0; t < T_LEN; ++t) {
        phase_fn<1, 0>(Xs, Hs, acc1, acc0, cst0, xr0, xga0, t, lane,
                       xoff0, xoff1, hoff0, hoff1, bfr, bias2);
        __syncthreads();
        phase_fn<0, 1>(Xs, Hs, acc0, acc1, cst1, xr1, xga1, t, lane,
                       xoff0, xoff1, hoff0, hoff1, bfr, bias2);
        __syncthreads();
    }

    // ---- FC epilogue: gather h_T from frag-major fp16 tiles ----
    for (int idx = tid; idx < M_BLK * OUT_SZ; idx += NTHREADS) {
        const int row = idx >> 3;
        const int o   = idx & 7;
        const int g   = row >> 5;
        const int lr  = row & 31;
        const int r   = lr >> 4, arle = lr & 7, sube = (lr >> 3) & 1;
        const uint32_t* Hg = Hs + g * 1024;
        const float* wf = W_fc + o * H_SZ;
        float s = b_fc[o];
        #pragma unroll
        for (int cc = 0; cc < 32; ++cc) {
            const int c  = cc * 2;
            const int qh = c >> 4;
            const int p  = (c & 15) >> 1;
            uint32_t wv = Hg[(qh * 2 + r) * 128 + (arle * 4 + (p & 3)) * 4 + sube + 2 * (p >> 2)];
            __half2 h2 = *reinterpret_cast<__half2*>(&wv);
            float2 f2 = __half22float2(h2);
            s += f2.x * wf[c] + f2.y * wf[c + 1];
        }
        out[(size_t)(row0 + row) * OUT_SZ + o] = s;
    }
}

extern "C" void kernel_launch(void* const* d_in, const int* in_sizes, int n_in,
                              void* d_out, int out_size) {
    const float* x    = (const float*)d_in[0];
    const float* W_ih = (const float*)d_in[1];
    const float* W_hh = (const float*)d_in[2];
    const float* b_ih = (const float*)d_in[3];
    const float* b_hh = (const float*)d_in[4];
    const float* W_fc = (const float*)d_in[5];
    const float* b_fc = (const float*)d_in[6];
    float* out = (float*)d_out;

    lstm_fp16_kernel<<<B_TOT / M_BLK, NTHREADS>>>(x, W_ih, W_hh, b_ih, b_hh, W_fc, b_fc, out);
}